// round 12
// baseline (speedup 1.0000x reference)
#include <cuda_runtime.h>
#include <cuda_bf16.h>
#include <cstdint>
#include <cstddef>

#define B_    256
#define D_    512
#define K_    128000
#define N_    100000
#define TOPK_  5
#define TOPKP_ 10
#define CAND_  32
#define TH_    8
#define FLTMAX 3.402823466e+38f

// GEMM tiling: BM=256, BN=128, BK=32, 16 warps (4M x 4N), warp tile 64x32
#define BN 128
#define ASTG  20480                 // A stage bytes: 256 rows * 80
#define BSTG  10240                 // B (bf16) stage bytes: 128 rows * 80
#define BOFF  (4 * ASTG)            // 81920
#define GSMEM (4 * ASTG + 2 * BSTG) // 102400

// ---------------- device scratch ----------------
__device__ __align__(16) float g_St [32768000];   // fp32 scores, mode 0
__device__ __align__(16) float g_Stp[32768000];   // fp32 scores, mode 1
__device__ __align__(16) float g_tnorm[B_ * D_];
__device__ __align__(16) float g_qnorm[B_ * D_];
__device__ __align__(16) float g_ct   [B_ * D_];
__device__ __align__(16) __nv_bfloat16 g_tb[B_ * D_];
__device__ __align__(16) __nv_bfloat16 g_cb[B_ * D_];
__device__ int   g_eq[N_];
__device__ int   g_cand1[B_ * CAND_], g_cand2[B_ * CAND_];
__device__ int   g_unidx[B_ * TOPK_], g_idxp[B_ * TOPKP_];
__device__ float g_pb_un[B_], g_pb_con[B_], g_pb_pur[B_];

// ---------------- MMA / cp.async helpers ----------------
__device__ __forceinline__ void ldsm4(uint32_t* r, uint32_t addr) {
    asm volatile("ldmatrix.sync.aligned.m8n8.x4.shared.b16 {%0,%1,%2,%3}, [%4];"
        : "=r"(r[0]), "=r"(r[1]), "=r"(r[2]), "=r"(r[3]) : "r"(addr));
}
__device__ __forceinline__ void mma16816(float* c,
        uint32_t a0, uint32_t a1, uint32_t a2, uint32_t a3,
        uint32_t b0, uint32_t b1) {
    asm volatile(
        "mma.sync.aligned.m16n8k16.row.col.f32.bf16.bf16.f32 "
        "{%0,%1,%2,%3}, {%4,%5,%6,%7}, {%8,%9}, {%0,%1,%2,%3};"
        : "+f"(c[0]), "+f"(c[1]), "+f"(c[2]), "+f"(c[3])
        : "r"(a0), "r"(a1), "r"(a2), "r"(a3), "r"(b0), "r"(b1));
}
#define CP_ASYNC16(dst_u32, src_ptr) \
    asm volatile("cp.async.cg.shared.global [%0], [%1], 16;" \
        :: "r"(dst_u32), "l"(src_ptr))
#define CP_COMMIT() asm volatile("cp.async.commit_group;" ::: "memory")
#define CP_WAIT0()  asm volatile("cp.async.wait_group 0;" ::: "memory")
#define CP_WAIT1()  asm volatile("cp.async.wait_group 1;" ::: "memory")
#define CP_WAIT2()  asm volatile("cp.async.wait_group 2;" ::: "memory")

// ---------------- prep kernels ----------------
__global__ void k_eq_copy(const int* __restrict__ pq) {
    int i = blockIdx.x * blockDim.x + threadIdx.x;
    if (i < N_) g_eq[i] = pq[i];
}
// merged: flip eq at indices[b] + normalize q/t (+bf16 t) + gather ct_prime (+bf16)
__global__ void k_prep(const float* __restrict__ query, const float* __restrict__ ctgt,
                       const float* __restrict__ pool, const int* __restrict__ indices,
                       const int* __restrict__ pq) {
    int b = blockIdx.x, t = threadIdx.x;
    __shared__ float red[256];
    if (t == 0) {                     // flip (idempotent across duplicate indices)
        int n = indices[b];
        g_eq[n] = 1 - pq[n];
    }
    if (t < 128) {                    // gather ct row; slot = flipped value directly
        int n = indices[b];
        int slot = 1 - pq[n];
        const float4* src = (const float4*)(pool + ((size_t)slot * N_ + (size_t)n) * D_);
        float4 v = src[t];
        ((float4*)(g_ct + b * D_))[t] = v;
        __nv_bfloat162 p0 = __floats2bfloat162_rn(v.x, v.y);
        __nv_bfloat162 p1 = __floats2bfloat162_rn(v.z, v.w);
        uint2 u; u.x = *(uint32_t*)&p0; u.y = *(uint32_t*)&p1;
        ((uint2*)(g_cb + b * D_))[t] = u;
    }
    float x0 = query[b * D_ + t], x1 = query[b * D_ + t + 256];
    red[t] = x0 * x0 + x1 * x1;
    __syncthreads();
    for (int s = 128; s > 0; s >>= 1) { if (t < s) red[t] += red[t + s]; __syncthreads(); }
    float nq = sqrtf(red[0]);
    __syncthreads();
    g_qnorm[b * D_ + t] = x0 / nq;
    g_qnorm[b * D_ + t + 256] = x1 / nq;
    float y0 = ctgt[b * D_ + t], y1 = ctgt[b * D_ + t + 256];
    red[t] = y0 * y0 + y1 * y1;
    __syncthreads();
    for (int s = 128; s > 0; s >>= 1) { if (t < s) red[t] += red[t + s]; __syncthreads(); }
    float nt = sqrtf(red[0]);
    __syncthreads();
    float t0 = y0 / nt, t1 = y1 / nt;
    g_tnorm[b * D_ + t] = t0;
    g_tnorm[b * D_ + t + 256] = t1;
    g_tb[b * D_ + t] = __float2bfloat16(t0);
    g_tb[b * D_ + t + 256] = __float2bfloat16(t1);
}

// ---------------- fused GEMM (512 threads, 16 warps), fp32 score output ----------------
__global__ __launch_bounds__(512, 1)
void k_gemm3(const float* __restrict__ queue, const float* __restrict__ pool,
             const int* __restrict__ indices, const int* __restrict__ index_queue) {
    extern __shared__ __align__(16) char smem[];
    __shared__ const float* rowp[BN];

    const int my   = blockIdx.y;
    const int tid  = threadIdx.x;
    const int lane = tid & 31, wid = tid >> 5;
    const int wm = wid >> 2, wn = wid & 3;          // 4 x 4 warp grid, tile 64x32
    const int bn = blockIdx.x * BN;
    const uint32_t smem_u = (uint32_t)__cvta_generic_to_shared(smem);

    const __nv_bfloat16* Ab = (my == 0) ? g_tb : g_cb;
    float* out = (my == 0) ? g_St : g_Stp;

    if (tid < BN) {
        int kg = bn + tid;
        const float* p;
        if (my == 0) {
            p = (kg < B_) ? (g_tnorm + kg * D_) : (queue + (size_t)kg * D_);
        } else {
            int ik = (kg < B_) ? indices[kg] : index_queue[kg];
            p = pool + ((size_t)g_eq[ik] * N_ + (size_t)ik) * D_;
        }
        rowp[tid] = p;
    }
    __syncthreads();

    float acc[4][4][4];
#pragma unroll
    for (int a = 0; a < 4; a++)
#pragma unroll
        for (int b = 0; b < 4; b++)
#pragma unroll
            for (int c = 0; c < 4; c++) acc[a][b][c] = 0.f;

    const int ar0 = tid >> 2, ac0 = tid & 3;
    const int ar1 = (tid + 512) >> 2, ac1 = (tid + 512) & 3;
    const int br0 = tid >> 3, bc0 = tid & 7;
    const int br1 = (tid + 512) >> 3, bc1 = (tid + 512) & 7;
    const float* bp0 = rowp[br0] + bc0 * 4;
    const float* bp1 = rowp[br1] + bc1 * 4;

#define ISSUE_A(s, kk) do { \
        uint32_t base_ = smem_u + (s) * ASTG; \
        CP_ASYNC16(base_ + ar0 * 80 + ac0 * 16, Ab + (size_t)ar0 * D_ + (kk) + ac0 * 8); \
        CP_ASYNC16(base_ + ar1 * 80 + ac1 * 16, Ab + (size_t)ar1 * D_ + (kk) + ac1 * 8); \
        CP_COMMIT(); \
    } while (0)

#define LOAD_B(kk) do { \
        fb[0] = *(const float4*)(bp0 + (kk)); \
        fb[1] = *(const float4*)(bp1 + (kk)); \
    } while (0)

#define STS_B(s) do { \
        char* base_ = smem + BOFF + (s) * BSTG; \
        { __nv_bfloat162 h0_ = __floats2bfloat162_rn(fb[0].x, fb[0].y); \
          __nv_bfloat162 h1_ = __floats2bfloat162_rn(fb[0].z, fb[0].w); \
          uint2 u_; u_.x = *(uint32_t*)&h0_; u_.y = *(uint32_t*)&h1_; \
          *(uint2*)(base_ + br0 * 80 + bc0 * 8) = u_; } \
        { __nv_bfloat162 h0_ = __floats2bfloat162_rn(fb[1].x, fb[1].y); \
          __nv_bfloat162 h1_ = __floats2bfloat162_rn(fb[1].z, fb[1].w); \
          uint2 u_; u_.x = *(uint32_t*)&h0_; u_.y = *(uint32_t*)&h1_; \
          *(uint2*)(base_ + br1 * 80 + bc1 * 8) = u_; } \
    } while (0)

    float4 fb[2];
    LOAD_B(0);
    ISSUE_A(0, 0); ISSUE_A(1, 32); ISSUE_A(2, 64);
    STS_B(0);
    LOAD_B(32);
    CP_WAIT2();
    __syncthreads();

    const int lrow = lane & 15, lhi = lane >> 4;
#pragma unroll 1
    for (int it = 0; it < 16; ++it) {
        const uint32_t As_u = smem_u + (it & 3) * ASTG;
        const uint32_t Bs_u = smem_u + BOFF + (it & 1) * BSTG;
#pragma unroll
        for (int ks = 0; ks < 2; ks++) {
            uint32_t af[4][4], bf[2][4];
#pragma unroll
            for (int mt = 0; mt < 4; mt++)
                ldsm4(af[mt], As_u + (wm * 64 + mt * 16 + lrow) * 80 + ks * 32 + lhi * 16);
#pragma unroll
            for (int np = 0; np < 2; np++)
                ldsm4(bf[np], Bs_u + (wn * 32 + np * 16 + lrow) * 80 + ks * 32 + lhi * 16);
#pragma unroll
            for (int mt = 0; mt < 4; mt++)
#pragma unroll
                for (int np = 0; np < 2; np++) {
                    mma16816(acc[mt][2 * np],
                             af[mt][0], af[mt][1], af[mt][2], af[mt][3],
                             bf[np][0], bf[np][2]);
                    mma16816(acc[mt][2 * np + 1],
                             af[mt][0], af[mt][1], af[mt][2], af[mt][3],
                             bf[np][1], bf[np][3]);
                }
        }
        if (it < 15) {
            STS_B((it + 1) & 1);
            if (it < 14) LOAD_B((it + 2) * 32);
            if (it + 3 < 16) ISSUE_A((it + 3) & 3, (it + 3) * 32);
            if (it < 13) CP_WAIT2(); else if (it == 13) CP_WAIT1(); else CP_WAIT0();
            __syncthreads();
        }
    }
#undef ISSUE_A
#undef LOAD_B
#undef STS_B

    // epilogue: dist = 2 - 2*ip, fp32 float2 stores
#pragma unroll
    for (int mt = 0; mt < 4; mt++) {
        int r0 = wm * 64 + mt * 16 + (lane >> 2);
#pragma unroll
        for (int nt = 0; nt < 4; nt++) {
            int c = bn + wn * 32 + nt * 8 + (lane & 3) * 2;
            float2 v0, v1;
            v0.x = 2.f - 2.f * acc[mt][nt][0];
            v0.y = 2.f - 2.f * acc[mt][nt][1];
            v1.x = 2.f - 2.f * acc[mt][nt][2];
            v1.y = 2.f - 2.f * acc[mt][nt][3];
            *(float2*)(out + (size_t)r0 * K_ + c)       = v0;
            *(float2*)(out + (size_t)(r0 + 8) * K_ + c) = v1;
        }
    }
}

// ---------------- approx top-CAND per row: batched group-min scan (MLP=8) ----------------
__device__ __forceinline__ void tk_ins(float xv, int k, float* v, int* id, float& thr) {
    if (xv < thr) {   // per-thread index increasing -> strict < keeps earliest
        int pos = TH_ - 1;
        while (pos > 0 && xv < v[pos - 1]) {
            v[pos] = v[pos - 1]; id[pos] = id[pos - 1]; pos--;
        }
        v[pos] = xv; id[pos] = k;
        thr = v[TH_ - 1];
    }
}
__device__ __forceinline__ float min4(float4 a) {
    return fminf(fminf(a.x, a.y), fminf(a.z, a.w));
}
__device__ __forceinline__ void grp_ins(float4 c, int k4, float* v, int* id, float& thr) {
    if (min4(c) < thr) {
        int kb = k4 * 4;
        tk_ins(c.x, kb + 0, v, id, thr);
        tk_ins(c.y, kb + 1, v, id, thr);
        tk_ins(c.z, kb + 2, v, id, thr);
        tk_ins(c.w, kb + 3, v, id, thr);
    }
}
__global__ __launch_bounds__(512)
void k_topk2(const float* __restrict__ Sa, const float* __restrict__ Sb,
             int* __restrict__ o1, int* __restrict__ o2) {
    const int NG4 = K_ / 4;           // 32000 float4 groups per row
    int b = blockIdx.x;
    const float* S = (blockIdx.y == 0) ? Sa : Sb;
    int* outIdx = (blockIdx.y == 0) ? o1 : o2;
    const float4* row = (const float4*)(S + (size_t)b * K_);
    float v[TH_]; int id[TH_];
#pragma unroll
    for (int i = 0; i < TH_; i++) { v[i] = FLTMAX; id[i] = 0x7fffffff; }
    float thr = FLTMAX;
    const float4 PADV = make_float4(FLTMAX, FLTMAX, FLTMAX, FLTMAX);
    const int t = threadIdx.x;

    // batch of 4 coalesced float4 loads per iteration; prefetch next batch (MLP 4-8).
    // per-thread group indices base+t+512j are strictly increasing across the scan.
    float4 c0, c1, c2, c3, n0, n1, n2, n3;
    {
        int k0 = t, k1 = t + 512, k2 = t + 1024, k3 = t + 1536;
        c0 = (k0 < NG4) ? row[k0] : PADV;
        c1 = (k1 < NG4) ? row[k1] : PADV;
        c2 = (k2 < NG4) ? row[k2] : PADV;
        c3 = (k3 < NG4) ? row[k3] : PADV;
    }
    for (int base = 0; base < NG4; base += 2048) {
        int nb = base + 2048;
        {
            int k0 = nb + t, k1 = k0 + 512, k2 = k0 + 1024, k3 = k0 + 1536;
            n0 = (k0 < NG4) ? row[k0] : PADV;
            n1 = (k1 < NG4) ? row[k1] : PADV;
            n2 = (k2 < NG4) ? row[k2] : PADV;
            n3 = (k3 < NG4) ? row[k3] : PADV;
        }
        // 16-way min filter (parallel tree), then rare per-group inserts
        float m = fminf(fminf(min4(c0), min4(c1)), fminf(min4(c2), min4(c3)));
        if (m < thr) {
            grp_ins(c0, base + t,        v, id, thr);
            grp_ins(c1, base + t + 512,  v, id, thr);
            grp_ins(c2, base + t + 1024, v, id, thr);
            grp_ins(c3, base + t + 1536, v, id, thr);
        }
        c0 = n0; c1 = n1; c2 = n2; c3 = n3;
    }

    __shared__ float swv[16]; __shared__ int swi[16];
    __shared__ int bwi_s;
    int hp = 0;
    for (int r = 0; r < CAND_; r++) {
        float mv = (hp < TH_) ? v[hp] : FLTMAX;
        int   mi = (hp < TH_) ? id[hp] : 0x7fffffff;
        for (int o = 16; o > 0; o >>= 1) {
            float ov = __shfl_down_sync(0xffffffffu, mv, o);
            int   oi = __shfl_down_sync(0xffffffffu, mi, o);
            if (ov < mv || (ov == mv && oi < mi)) { mv = ov; mi = oi; }
        }
        if ((t & 31) == 0) { swv[t >> 5] = mv; swi[t >> 5] = mi; }
        __syncthreads();
        if (t == 0) {
            float bv = swv[0]; int bi = swi[0];
            for (int w = 1; w < 16; w++)
                if (swv[w] < bv || (swv[w] == bv && swi[w] < bi)) { bv = swv[w]; bi = swi[w]; }
            bwi_s = bi;
            outIdx[b * CAND_ + r] = bi;
        }
        __syncthreads();
        if (hp < TH_ && id[hp] == bwi_s) hp++;
        __syncthreads();
    }
}

// ---------------- exact refine (merged): blockIdx.y = mode ----------------
__global__ void k_refine(const float* __restrict__ queue, const float* __restrict__ pool,
                         const int* __restrict__ indices, const int* __restrict__ index_queue) {
    int b = blockIdx.x, mode = blockIdx.y;
    int T = (mode == 0) ? TOPK_ : TOPKP_;
    const int* cand = (mode == 0) ? g_cand1 : g_cand2;
    int* outIdx = (mode == 0) ? g_unidx : g_idxp;
    int lane = threadIdx.x & 31, w = threadIdx.x >> 5;   // 8 warps
    __shared__ float sv[CAND_];
    const float* ar = (mode == 0) ? (g_tnorm + b * D_) : (g_ct + b * D_);
    for (int j = w; j < CAND_; j += 8) {
        int k = cand[b * CAND_ + j];
        const float* rk;
        if (mode == 0) rk = (k < B_) ? (g_tnorm + k * D_) : (queue + (size_t)k * D_);
        else {
            int ik = (k < B_) ? indices[k] : index_queue[k];
            rk = pool + ((size_t)g_eq[ik] * N_ + (size_t)ik) * D_;
        }
        float s = 0.f;
#pragma unroll
        for (int tt = 0; tt < 16; tt++) { int i = tt * 32 + lane; s += ar[i] * rk[i]; }
        for (int o = 16; o > 0; o >>= 1) s += __shfl_down_sync(0xffffffffu, s, o);
        if (lane == 0) sv[j] = 2.f - 2.f * s;
    }
    __syncthreads();
    if (threadIdx.x == 0) {
        float vl[CAND_]; int il[CAND_];
        for (int j = 0; j < CAND_; j++) { vl[j] = sv[j]; il[j] = cand[b * CAND_ + j]; }
        for (int r = 0; r < T; r++) {
            int best = r;
            for (int j = r + 1; j < CAND_; j++)
                if (vl[j] < vl[best] || (vl[j] == vl[best] && il[j] < il[best])) best = j;
            float tv = vl[r]; vl[r] = vl[best]; vl[best] = tv;
            int ti = il[r]; il[r] = il[best]; il[best] = ti;
            outIdx[b * T + r] = il[r];
        }
    }
}

// ---------------- final: exact con-select + loss dots + purity ----------------
__global__ void k_final(const float* __restrict__ queue,
                        const int* __restrict__ labels_bank,
                        const int* __restrict__ labels) {
    int b = blockIdx.x, t = threadIdx.x;
    __shared__ float red[256];
    __shared__ float pv[TOPKP_];
    __shared__ int conIdx[TOPK_];
    const float* qr = g_qnorm + b * D_;
    const float* tr = g_tnorm + b * D_;
    for (int j = 0; j < TOPKP_; j++) {
        int k = g_idxp[b * TOPKP_ + j];
        const float* rk = (k < B_) ? (g_tnorm + k * D_) : (queue + (size_t)k * D_);
        red[t] = tr[t] * rk[t] + tr[t + 256] * rk[t + 256];
        __syncthreads();
        for (int s = 128; s > 0; s >>= 1) { if (t < s) red[t] += red[t + s]; __syncthreads(); }
        if (t == 0) pv[j] = 2.f - 2.f * red[0];
        __syncthreads();
    }
    if (t == 0) {
        float vl[TOPKP_]; int il[TOPKP_];
        for (int j = 0; j < TOPKP_; j++) { vl[j] = pv[j]; il[j] = g_idxp[b * TOPKP_ + j]; }
        for (int r = 0; r < TOPK_; r++) {
            int best = r;
            for (int j = r + 1; j < TOPKP_; j++)
                if (vl[j] < vl[best] || (vl[j] == vl[best] && il[j] < il[best])) best = j;
            float tv = vl[r]; vl[r] = vl[best]; vl[best] = tv;
            int ti = il[r]; il[r] = il[best]; il[best] = ti;
            conIdx[r] = il[r];
        }
    }
    __syncthreads();
    __shared__ float s_un, s_con;
    __shared__ int s_match;
    if (t == 0) { s_un = 0.f; s_con = 0.f; s_match = 0; }
    __syncthreads();
    for (int j = 0; j < 2 * TOPK_; j++) {
        int k = (j < TOPK_) ? g_unidx[b * TOPK_ + j] : conIdx[j - TOPK_];
        const float* rk = (k < B_) ? (g_tnorm + k * D_) : (queue + (size_t)k * D_);
        red[t] = qr[t] * rk[t] + qr[t + 256] * rk[t + 256];
        __syncthreads();
        for (int s = 128; s > 0; s >>= 1) { if (t < s) red[t] += red[t + s]; __syncthreads(); }
        if (t == 0) {
            float d = 2.f - 2.f * red[0];
            if (j < TOPK_) {
                s_un += d;
                int lab = (k < B_) ? labels[k] : labels_bank[k];
                if (lab == labels[b]) s_match++;
            } else {
                s_con += d;
            }
        }
        __syncthreads();
    }
    if (t == 0) {
        g_pb_un[b]  = s_un / (float)TOPK_;
        g_pb_con[b] = s_con / (float)TOPK_;
        g_pb_pur[b] = (float)s_match / (float)TOPK_;
    }
}

__global__ void k_finalize(float* __restrict__ out, int out_size) {
    int t = threadIdx.x;   // 256 threads
    __shared__ float ru[256], rc[256], rp[256];
    ru[t] = g_pb_un[t]; rc[t] = g_pb_con[t]; rp[t] = g_pb_pur[t];
    __syncthreads();
    for (int s = 128; s > 0; s >>= 1) {
        if (t < s) { ru[t] += ru[t + s]; rc[t] += rc[t + s]; rp[t] += rp[t + s]; }
        __syncthreads();
    }
    if (t == 0) {
        float loss = (rc[0] / (float)B_ + ru[0] / (float)B_) * 0.5f;
        out[0] = loss;
        if (out_size > 1) out[1] = rp[0] / (float)B_;
    }
}

// ---------------- launch ----------------
extern "C" void kernel_launch(void* const* d_in, const int* in_sizes, int n_in,
                              void* d_out, int out_size) {
    const float* query       = (const float*)d_in[0];
    const float* ctgt        = (const float*)d_in[1];
    const float* queue       = (const float*)d_in[2];
    const float* pool        = (const float*)d_in[3];
    const int*   labels_bank = (const int*)d_in[4];
    const int*   index_queue = (const int*)d_in[5];
    const int*   pool_qindex = (const int*)d_in[6];
    const int*   labels      = (const int*)d_in[7];
    const int*   indices     = (const int*)d_in[8];

    float* St_ptr;  cudaGetSymbolAddress((void**)&St_ptr,  g_St);
    float* Stp_ptr; cudaGetSymbolAddress((void**)&Stp_ptr, g_Stp);
    int* c1_ptr; cudaGetSymbolAddress((void**)&c1_ptr, g_cand1);
    int* c2_ptr; cudaGetSymbolAddress((void**)&c2_ptr, g_cand2);

    cudaFuncSetAttribute(k_gemm3, cudaFuncAttributeMaxDynamicSharedMemorySize, GSMEM);

    // launch #1
    k_eq_copy<<<(N_ + 255) / 256, 256>>>(pool_qindex);
    // launch #2
    k_prep<<<B_, 256>>>(query, ctgt, pool, indices, pool_qindex);
    // launch #3
    dim3 gg(K_ / BN, 2);
    k_gemm3<<<gg, 512, GSMEM>>>(queue, pool, indices, index_queue);
    // launch #4  <-- ncu capture slot
    dim3 gt(B_, 2);
    k_topk2<<<gt, 512>>>(St_ptr, Stp_ptr, c1_ptr, c2_ptr);
    // launch #5
    dim3 gr(B_, 2);
    k_refine<<<gr, 2 * 128>>>(queue, pool, indices, index_queue);
    // launch #6
    k_final<<<B_, 256>>>(queue, labels_bank, labels);
    // launch #7
    k_finalize<<<1, 256>>>((float*)d_out, out_size);
}

// round 13
// speedup vs baseline: 1.3083x; 1.3083x over previous
#include <cuda_runtime.h>
#include <cuda_bf16.h>
#include <cstdint>
#include <cstddef>

#define B_    256
#define D_    512
#define K_    128000
#define N_    100000
#define TOPK_  5
#define TOPKP_ 10
#define CAND_  32
#define TH_    8
#define TKT    640      // topk threads: 32000 float4 groups = 640 * 50 exactly
#define FLTMAX 3.402823466e+38f

// GEMM tiling: BM=256, BN=128, BK=32, 16 warps (4M x 4N), warp tile 64x32
#define BN 128
#define ASTG  20480                 // A stage bytes: 256 rows * 80
#define BSTG  10240                 // B (bf16) stage bytes: 128 rows * 80
#define BOFF  (4 * ASTG)            // 81920
#define GSMEM (4 * ASTG + 2 * BSTG) // 102400

// ---------------- device scratch ----------------
__device__ __align__(16) float g_St [32768000];   // fp32 scores, mode 0
__device__ __align__(16) float g_Stp[32768000];   // fp32 scores, mode 1
__device__ __align__(16) float g_tnorm[B_ * D_];
__device__ __align__(16) float g_qnorm[B_ * D_];
__device__ __align__(16) float g_ct   [B_ * D_];
__device__ __align__(16) __nv_bfloat16 g_tb[B_ * D_];
__device__ __align__(16) __nv_bfloat16 g_cb[B_ * D_];
__device__ int   g_eq[N_];
__device__ int   g_cand1[B_ * CAND_], g_cand2[B_ * CAND_];
__device__ int   g_unidx[B_ * TOPK_], g_idxp[B_ * TOPKP_];
__device__ float g_pb_un[B_], g_pb_con[B_], g_pb_pur[B_];

// ---------------- MMA / cp.async helpers ----------------
__device__ __forceinline__ void ldsm4(uint32_t* r, uint32_t addr) {
    asm volatile("ldmatrix.sync.aligned.m8n8.x4.shared.b16 {%0,%1,%2,%3}, [%4];"
        : "=r"(r[0]), "=r"(r[1]), "=r"(r[2]), "=r"(r[3]) : "r"(addr));
}
__device__ __forceinline__ void mma16816(float* c,
        uint32_t a0, uint32_t a1, uint32_t a2, uint32_t a3,
        uint32_t b0, uint32_t b1) {
    asm volatile(
        "mma.sync.aligned.m16n8k16.row.col.f32.bf16.bf16.f32 "
        "{%0,%1,%2,%3}, {%4,%5,%6,%7}, {%8,%9}, {%0,%1,%2,%3};"
        : "+f"(c[0]), "+f"(c[1]), "+f"(c[2]), "+f"(c[3])
        : "r"(a0), "r"(a1), "r"(a2), "r"(a3), "r"(b0), "r"(b1));
}
#define CP_ASYNC16(dst_u32, src_ptr) \
    asm volatile("cp.async.cg.shared.global [%0], [%1], 16;" \
        :: "r"(dst_u32), "l"(src_ptr))
#define CP_COMMIT() asm volatile("cp.async.commit_group;" ::: "memory")
#define CP_WAIT0()  asm volatile("cp.async.wait_group 0;" ::: "memory")
#define CP_WAIT1()  asm volatile("cp.async.wait_group 1;" ::: "memory")
#define CP_WAIT2()  asm volatile("cp.async.wait_group 2;" ::: "memory")

// ---------------- prep kernels ----------------
__global__ void k_eq_copy(const int* __restrict__ pq) {
    int i = blockIdx.x * blockDim.x + threadIdx.x;
    if (i < N_) g_eq[i] = pq[i];
}
// merged: flip eq at indices[b] + normalize q/t (+bf16 t) + gather ct_prime (+bf16)
__global__ void k_prep(const float* __restrict__ query, const float* __restrict__ ctgt,
                       const float* __restrict__ pool, const int* __restrict__ indices,
                       const int* __restrict__ pq) {
    int b = blockIdx.x, t = threadIdx.x;
    __shared__ float red[256];
    if (t == 0) {                     // flip (idempotent across duplicate indices)
        int n = indices[b];
        g_eq[n] = 1 - pq[n];
    }
    if (t < 128) {                    // gather ct row; slot = flipped value directly
        int n = indices[b];
        int slot = 1 - pq[n];
        const float4* src = (const float4*)(pool + ((size_t)slot * N_ + (size_t)n) * D_);
        float4 v = src[t];
        ((float4*)(g_ct + b * D_))[t] = v;
        __nv_bfloat162 p0 = __floats2bfloat162_rn(v.x, v.y);
        __nv_bfloat162 p1 = __floats2bfloat162_rn(v.z, v.w);
        uint2 u; u.x = *(uint32_t*)&p0; u.y = *(uint32_t*)&p1;
        ((uint2*)(g_cb + b * D_))[t] = u;
    }
    float x0 = query[b * D_ + t], x1 = query[b * D_ + t + 256];
    red[t] = x0 * x0 + x1 * x1;
    __syncthreads();
    for (int s = 128; s > 0; s >>= 1) { if (t < s) red[t] += red[t + s]; __syncthreads(); }
    float nq = sqrtf(red[0]);
    __syncthreads();
    g_qnorm[b * D_ + t] = x0 / nq;
    g_qnorm[b * D_ + t + 256] = x1 / nq;
    float y0 = ctgt[b * D_ + t], y1 = ctgt[b * D_ + t + 256];
    red[t] = y0 * y0 + y1 * y1;
    __syncthreads();
    for (int s = 128; s > 0; s >>= 1) { if (t < s) red[t] += red[t + s]; __syncthreads(); }
    float nt = sqrtf(red[0]);
    __syncthreads();
    float t0 = y0 / nt, t1 = y1 / nt;
    g_tnorm[b * D_ + t] = t0;
    g_tnorm[b * D_ + t + 256] = t1;
    g_tb[b * D_ + t] = __float2bfloat16(t0);
    g_tb[b * D_ + t + 256] = __float2bfloat16(t1);
}

// ---------------- fused GEMM (512 threads, 16 warps), fp32 score output ----------------
__global__ __launch_bounds__(512, 1)
void k_gemm3(const float* __restrict__ queue, const float* __restrict__ pool,
             const int* __restrict__ indices, const int* __restrict__ index_queue) {
    extern __shared__ __align__(16) char smem[];
    __shared__ const float* rowp[BN];

    const int my   = blockIdx.y;
    const int tid  = threadIdx.x;
    const int lane = tid & 31, wid = tid >> 5;
    const int wm = wid >> 2, wn = wid & 3;          // 4 x 4 warp grid, tile 64x32
    const int bn = blockIdx.x * BN;
    const uint32_t smem_u = (uint32_t)__cvta_generic_to_shared(smem);

    const __nv_bfloat16* Ab = (my == 0) ? g_tb : g_cb;
    float* out = (my == 0) ? g_St : g_Stp;

    if (tid < BN) {
        int kg = bn + tid;
        const float* p;
        if (my == 0) {
            p = (kg < B_) ? (g_tnorm + kg * D_) : (queue + (size_t)kg * D_);
        } else {
            int ik = (kg < B_) ? indices[kg] : index_queue[kg];
            p = pool + ((size_t)g_eq[ik] * N_ + (size_t)ik) * D_;
        }
        rowp[tid] = p;
    }
    __syncthreads();

    float acc[4][4][4];
#pragma unroll
    for (int a = 0; a < 4; a++)
#pragma unroll
        for (int b = 0; b < 4; b++)
#pragma unroll
            for (int c = 0; c < 4; c++) acc[a][b][c] = 0.f;

    const int ar0 = tid >> 2, ac0 = tid & 3;
    const int ar1 = (tid + 512) >> 2, ac1 = (tid + 512) & 3;
    const int br0 = tid >> 3, bc0 = tid & 7;
    const int br1 = (tid + 512) >> 3, bc1 = (tid + 512) & 7;
    const float* bp0 = rowp[br0] + bc0 * 4;
    const float* bp1 = rowp[br1] + bc1 * 4;

#define ISSUE_A(s, kk) do { \
        uint32_t base_ = smem_u + (s) * ASTG; \
        CP_ASYNC16(base_ + ar0 * 80 + ac0 * 16, Ab + (size_t)ar0 * D_ + (kk) + ac0 * 8); \
        CP_ASYNC16(base_ + ar1 * 80 + ac1 * 16, Ab + (size_t)ar1 * D_ + (kk) + ac1 * 8); \
        CP_COMMIT(); \
    } while (0)

#define LOAD_B(kk) do { \
        fb[0] = *(const float4*)(bp0 + (kk)); \
        fb[1] = *(const float4*)(bp1 + (kk)); \
    } while (0)

#define STS_B(s) do { \
        char* base_ = smem + BOFF + (s) * BSTG; \
        { __nv_bfloat162 h0_ = __floats2bfloat162_rn(fb[0].x, fb[0].y); \
          __nv_bfloat162 h1_ = __floats2bfloat162_rn(fb[0].z, fb[0].w); \
          uint2 u_; u_.x = *(uint32_t*)&h0_; u_.y = *(uint32_t*)&h1_; \
          *(uint2*)(base_ + br0 * 80 + bc0 * 8) = u_; } \
        { __nv_bfloat162 h0_ = __floats2bfloat162_rn(fb[1].x, fb[1].y); \
          __nv_bfloat162 h1_ = __floats2bfloat162_rn(fb[1].z, fb[1].w); \
          uint2 u_; u_.x = *(uint32_t*)&h0_; u_.y = *(uint32_t*)&h1_; \
          *(uint2*)(base_ + br1 * 80 + bc1 * 8) = u_; } \
    } while (0)

    float4 fb[2];
    LOAD_B(0);
    ISSUE_A(0, 0); ISSUE_A(1, 32); ISSUE_A(2, 64);
    STS_B(0);
    LOAD_B(32);
    CP_WAIT2();
    __syncthreads();

    const int lrow = lane & 15, lhi = lane >> 4;
#pragma unroll 1
    for (int it = 0; it < 16; ++it) {
        const uint32_t As_u = smem_u + (it & 3) * ASTG;
        const uint32_t Bs_u = smem_u + BOFF + (it & 1) * BSTG;
#pragma unroll
        for (int ks = 0; ks < 2; ks++) {
            uint32_t af[4][4], bf[2][4];
#pragma unroll
            for (int mt = 0; mt < 4; mt++)
                ldsm4(af[mt], As_u + (wm * 64 + mt * 16 + lrow) * 80 + ks * 32 + lhi * 16);
#pragma unroll
            for (int np = 0; np < 2; np++)
                ldsm4(bf[np], Bs_u + (wn * 32 + np * 16 + lrow) * 80 + ks * 32 + lhi * 16);
#pragma unroll
            for (int mt = 0; mt < 4; mt++)
#pragma unroll
                for (int np = 0; np < 2; np++) {
                    mma16816(acc[mt][2 * np],
                             af[mt][0], af[mt][1], af[mt][2], af[mt][3],
                             bf[np][0], bf[np][2]);
                    mma16816(acc[mt][2 * np + 1],
                             af[mt][0], af[mt][1], af[mt][2], af[mt][3],
                             bf[np][1], bf[np][3]);
                }
        }
        if (it < 15) {
            STS_B((it + 1) & 1);
            if (it < 14) LOAD_B((it + 2) * 32);
            if (it + 3 < 16) ISSUE_A((it + 3) & 3, (it + 3) * 32);
            if (it < 13) CP_WAIT2(); else if (it == 13) CP_WAIT1(); else CP_WAIT0();
            __syncthreads();
        }
    }
#undef ISSUE_A
#undef LOAD_B
#undef STS_B

    // epilogue: dist = 2 - 2*ip, fp32 float2 stores
#pragma unroll
    for (int mt = 0; mt < 4; mt++) {
        int r0 = wm * 64 + mt * 16 + (lane >> 2);
#pragma unroll
        for (int nt = 0; nt < 4; nt++) {
            int c = bn + wn * 32 + nt * 8 + (lane & 3) * 2;
            float2 v0, v1;
            v0.x = 2.f - 2.f * acc[mt][nt][0];
            v0.y = 2.f - 2.f * acc[mt][nt][1];
            v1.x = 2.f - 2.f * acc[mt][nt][2];
            v1.y = 2.f - 2.f * acc[mt][nt][3];
            *(float2*)(out + (size_t)r0 * K_ + c)       = v0;
            *(float2*)(out + (size_t)(r0 + 8) * K_ + c) = v1;
        }
    }
}

// ---------------- approx top-CAND per row: branch-free tiled scan ----------------
// 640 threads x 50 iterations == 32000 float4 groups: NO bounds checks anywhere.
__device__ __forceinline__ void tk_ins(float xv, int k, float* v, int* id, float& thr) {
    if (xv < thr) {   // per-thread index increasing -> strict < keeps earliest
        int pos = TH_ - 1;
        while (pos > 0 && xv < v[pos - 1]) {
            v[pos] = v[pos - 1]; id[pos] = id[pos - 1]; pos--;
        }
        v[pos] = xv; id[pos] = k;
        thr = v[TH_ - 1];
    }
}
__device__ __forceinline__ void grp4(float4 c, int g, float* v, int* id, float& thr) {
    float m = fminf(fminf(c.x, c.y), fminf(c.z, c.w));
    if (m < thr) {                     // rare after warmup
        int kb = g * 4;
        tk_ins(c.x, kb + 0, v, id, thr);
        tk_ins(c.y, kb + 1, v, id, thr);
        tk_ins(c.z, kb + 2, v, id, thr);
        tk_ins(c.w, kb + 3, v, id, thr);
    }
}
__global__ __launch_bounds__(TKT)
void k_topk2(const float* __restrict__ Sa, const float* __restrict__ Sb,
             int* __restrict__ o1, int* __restrict__ o2) {
    int b = blockIdx.x;
    const float* S = (blockIdx.y == 0) ? Sa : Sb;
    int* outIdx = (blockIdx.y == 0) ? o1 : o2;
    const float4* row = (const float4*)(S + (size_t)b * K_);
    const int t = threadIdx.x;
    float v[TH_]; int id[TH_];
#pragma unroll
    for (int i = 0; i < TH_; i++) { v[i] = FLTMAX; id[i] = 0x7fffffff; }
    float thr = FLTMAX;

    float4 cur = row[t];
#pragma unroll 1
    for (int j = 0; j < 49; ++j) {
        float4 nxt = row[t + (j + 1) * TKT];   // always in range (j+1 <= 49)
        grp4(cur, t + j * TKT, v, id, thr);
        cur = nxt;
    }
    grp4(cur, t + 49 * TKT, v, id, thr);       // peeled last iteration

    __shared__ float swv[20]; __shared__ int swi[20];
    __shared__ int bwi_s;
    int hp = 0;
    for (int r = 0; r < CAND_; r++) {
        float mv = (hp < TH_) ? v[hp] : FLTMAX;
        int   mi = (hp < TH_) ? id[hp] : 0x7fffffff;
        for (int o = 16; o > 0; o >>= 1) {
            float ov = __shfl_down_sync(0xffffffffu, mv, o);
            int   oi = __shfl_down_sync(0xffffffffu, mi, o);
            if (ov < mv || (ov == mv && oi < mi)) { mv = ov; mi = oi; }
        }
        if ((t & 31) == 0) { swv[t >> 5] = mv; swi[t >> 5] = mi; }
        __syncthreads();
        if (t == 0) {
            float bv = swv[0]; int bi = swi[0];
            for (int w = 1; w < 20; w++)
                if (swv[w] < bv || (swv[w] == bv && swi[w] < bi)) { bv = swv[w]; bi = swi[w]; }
            bwi_s = bi;
            outIdx[b * CAND_ + r] = bi;
        }
        __syncthreads();
        if (hp < TH_ && id[hp] == bwi_s) hp++;
        __syncthreads();
    }
}

// ---------------- exact refine (merged): blockIdx.y = mode ----------------
__global__ void k_refine(const float* __restrict__ queue, const float* __restrict__ pool,
                         const int* __restrict__ indices, const int* __restrict__ index_queue) {
    int b = blockIdx.x, mode = blockIdx.y;
    int T = (mode == 0) ? TOPK_ : TOPKP_;
    const int* cand = (mode == 0) ? g_cand1 : g_cand2;
    int* outIdx = (mode == 0) ? g_unidx : g_idxp;
    int lane = threadIdx.x & 31, w = threadIdx.x >> 5;   // 8 warps
    __shared__ float sv[CAND_];
    const float* ar = (mode == 0) ? (g_tnorm + b * D_) : (g_ct + b * D_);
    for (int j = w; j < CAND_; j += 8) {
        int k = cand[b * CAND_ + j];
        const float* rk;
        if (mode == 0) rk = (k < B_) ? (g_tnorm + k * D_) : (queue + (size_t)k * D_);
        else {
            int ik = (k < B_) ? indices[k] : index_queue[k];
            rk = pool + ((size_t)g_eq[ik] * N_ + (size_t)ik) * D_;
        }
        float s = 0.f;
#pragma unroll
        for (int tt = 0; tt < 16; tt++) { int i = tt * 32 + lane; s += ar[i] * rk[i]; }
        for (int o = 16; o > 0; o >>= 1) s += __shfl_down_sync(0xffffffffu, s, o);
        if (lane == 0) sv[j] = 2.f - 2.f * s;
    }
    __syncthreads();
    if (threadIdx.x == 0) {
        float vl[CAND_]; int il[CAND_];
        for (int j = 0; j < CAND_; j++) { vl[j] = sv[j]; il[j] = cand[b * CAND_ + j]; }
        for (int r = 0; r < T; r++) {
            int best = r;
            for (int j = r + 1; j < CAND_; j++)
                if (vl[j] < vl[best] || (vl[j] == vl[best] && il[j] < il[best])) best = j;
            float tv = vl[r]; vl[r] = vl[best]; vl[best] = tv;
            int ti = il[r]; il[r] = il[best]; il[best] = ti;
            outIdx[b * T + r] = il[r];
        }
    }
}

// ---------------- final: exact con-select + loss dots + purity ----------------
__global__ void k_final(const float* __restrict__ queue,
                        const int* __restrict__ labels_bank,
                        const int* __restrict__ labels) {
    int b = blockIdx.x, t = threadIdx.x;
    __shared__ float red[256];
    __shared__ float pv[TOPKP_];
    __shared__ int conIdx[TOPK_];
    const float* qr = g_qnorm + b * D_;
    const float* tr = g_tnorm + b * D_;
    for (int j = 0; j < TOPKP_; j++) {
        int k = g_idxp[b * TOPKP_ + j];
        const float* rk = (k < B_) ? (g_tnorm + k * D_) : (queue + (size_t)k * D_);
        red[t] = tr[t] * rk[t] + tr[t + 256] * rk[t + 256];
        __syncthreads();
        for (int s = 128; s > 0; s >>= 1) { if (t < s) red[t] += red[t + s]; __syncthreads(); }
        if (t == 0) pv[j] = 2.f - 2.f * red[0];
        __syncthreads();
    }
    if (t == 0) {
        float vl[TOPKP_]; int il[TOPKP_];
        for (int j = 0; j < TOPKP_; j++) { vl[j] = pv[j]; il[j] = g_idxp[b * TOPKP_ + j]; }
        for (int r = 0; r < TOPK_; r++) {
            int best = r;
            for (int j = r + 1; j < TOPKP_; j++)
                if (vl[j] < vl[best] || (vl[j] == vl[best] && il[j] < il[best])) best = j;
            float tv = vl[r]; vl[r] = vl[best]; vl[best] = tv;
            int ti = il[r]; il[r] = il[best]; il[best] = ti;
            conIdx[r] = il[r];
        }
    }
    __syncthreads();
    __shared__ float s_un, s_con;
    __shared__ int s_match;
    if (t == 0) { s_un = 0.f; s_con = 0.f; s_match = 0; }
    __syncthreads();
    for (int j = 0; j < 2 * TOPK_; j++) {
        int k = (j < TOPK_) ? g_unidx[b * TOPK_ + j] : conIdx[j - TOPK_];
        const float* rk = (k < B_) ? (g_tnorm + k * D_) : (queue + (size_t)k * D_);
        red[t] = qr[t] * rk[t] + qr[t + 256] * rk[t + 256];
        __syncthreads();
        for (int s = 128; s > 0; s >>= 1) { if (t < s) red[t] += red[t + s]; __syncthreads(); }
        if (t == 0) {
            float d = 2.f - 2.f * red[0];
            if (j < TOPK_) {
                s_un += d;
                int lab = (k < B_) ? labels[k] : labels_bank[k];
                if (lab == labels[b]) s_match++;
            } else {
                s_con += d;
            }
        }
        __syncthreads();
    }
    if (t == 0) {
        g_pb_un[b]  = s_un / (float)TOPK_;
        g_pb_con[b] = s_con / (float)TOPK_;
        g_pb_pur[b] = (float)s_match / (float)TOPK_;
    }
}

__global__ void k_finalize(float* __restrict__ out, int out_size) {
    int t = threadIdx.x;   // 256 threads
    __shared__ float ru[256], rc[256], rp[256];
    ru[t] = g_pb_un[t]; rc[t] = g_pb_con[t]; rp[t] = g_pb_pur[t];
    __syncthreads();
    for (int s = 128; s > 0; s >>= 1) {
        if (t < s) { ru[t] += ru[t + s]; rc[t] += rc[t + s]; rp[t] += rp[t + s]; }
        __syncthreads();
    }
    if (t == 0) {
        float loss = (rc[0] / (float)B_ + ru[0] / (float)B_) * 0.5f;
        out[0] = loss;
        if (out_size > 1) out[1] = rp[0] / (float)B_;
    }
}

// ---------------- launch ----------------
extern "C" void kernel_launch(void* const* d_in, const int* in_sizes, int n_in,
                              void* d_out, int out_size) {
    const float* query       = (const float*)d_in[0];
    const float* ctgt        = (const float*)d_in[1];
    const float* queue       = (const float*)d_in[2];
    const float* pool        = (const float*)d_in[3];
    const int*   labels_bank = (const int*)d_in[4];
    const int*   index_queue = (const int*)d_in[5];
    const int*   pool_qindex = (const int*)d_in[6];
    const int*   labels      = (const int*)d_in[7];
    const int*   indices     = (const int*)d_in[8];

    float* St_ptr;  cudaGetSymbolAddress((void**)&St_ptr,  g_St);
    float* Stp_ptr; cudaGetSymbolAddress((void**)&Stp_ptr, g_Stp);
    int* c1_ptr; cudaGetSymbolAddress((void**)&c1_ptr, g_cand1);
    int* c2_ptr; cudaGetSymbolAddress((void**)&c2_ptr, g_cand2);

    cudaFuncSetAttribute(k_gemm3, cudaFuncAttributeMaxDynamicSharedMemorySize, GSMEM);

    // launch #1
    k_eq_copy<<<(N_ + 255) / 256, 256>>>(pool_qindex);
    // launch #2
    k_prep<<<B_, 256>>>(query, ctgt, pool, indices, pool_qindex);
    // launch #3
    dim3 gg(K_ / BN, 2);
    k_gemm3<<<gg, 512, GSMEM>>>(queue, pool, indices, index_queue);
    // launch #4  <-- ncu capture slot
    dim3 gt(B_, 2);
    k_topk2<<<gt, TKT>>>(St_ptr, Stp_ptr, c1_ptr, c2_ptr);
    // launch #5
    dim3 gr(B_, 2);
    k_refine<<<gr, 256>>>(queue, pool, indices, index_queue);
    // launch #6
    k_final<<<B_, 256>>>(queue, labels_bank, labels);
    // launch #7
    k_finalize<<<1, 256>>>((float*)d_out, out_size);
}

// round 14
// speedup vs baseline: 2.1101x; 1.6129x over previous
#include <cuda_runtime.h>
#include <cuda_bf16.h>
#include <cstdint>
#include <cstddef>

#define B_    256
#define D_    512
#define K_    128000
#define N_    100000
#define TOPK_  5
#define TOPKP_ 10
#define CAND_  32
#define TH_    8
#define FLTMAX 3.402823466e+38f

// GEMM tiling: BM=256, BN=128, BK=32, 16 warps (4M x 4N), warp tile 64x32
#define BN 128
#define ASTG  20480                 // A stage bytes: 256 rows * 80
#define BSTG  10240                 // B (bf16) stage bytes: 128 rows * 80
#define BOFF  (4 * ASTG)            // 81920
#define GSMEM (4 * ASTG + 2 * BSTG) // 102400

// ---------------- device scratch ----------------
__device__ __align__(16) float g_St [32768000];   // fp32 scores, mode 0
__device__ __align__(16) float g_Stp[32768000];   // fp32 scores, mode 1
__device__ __align__(16) float g_tnorm[B_ * D_];
__device__ __align__(16) float g_qnorm[B_ * D_];
__device__ __align__(16) float g_ct   [B_ * D_];
__device__ __align__(16) __nv_bfloat16 g_tb[B_ * D_];
__device__ __align__(16) __nv_bfloat16 g_cb[B_ * D_];
__device__ int   g_eq[N_];
__device__ int   g_cand1[B_ * CAND_], g_cand2[B_ * CAND_];
__device__ int   g_unidx[B_ * TOPK_], g_idxp[B_ * TOPKP_];
__device__ float g_pb_un[B_], g_pb_con[B_], g_pb_pur[B_];

// ---------------- MMA / cp.async helpers ----------------
__device__ __forceinline__ void ldsm4(uint32_t* r, uint32_t addr) {
    asm volatile("ldmatrix.sync.aligned.m8n8.x4.shared.b16 {%0,%1,%2,%3}, [%4];"
        : "=r"(r[0]), "=r"(r[1]), "=r"(r[2]), "=r"(r[3]) : "r"(addr));
}
__device__ __forceinline__ void mma16816(float* c,
        uint32_t a0, uint32_t a1, uint32_t a2, uint32_t a3,
        uint32_t b0, uint32_t b1) {
    asm volatile(
        "mma.sync.aligned.m16n8k16.row.col.f32.bf16.bf16.f32 "
        "{%0,%1,%2,%3}, {%4,%5,%6,%7}, {%8,%9}, {%0,%1,%2,%3};"
        : "+f"(c[0]), "+f"(c[1]), "+f"(c[2]), "+f"(c[3])
        : "r"(a0), "r"(a1), "r"(a2), "r"(a3), "r"(b0), "r"(b1));
}
#define CP_ASYNC16(dst_u32, src_ptr) \
    asm volatile("cp.async.cg.shared.global [%0], [%1], 16;" \
        :: "r"(dst_u32), "l"(src_ptr))
#define CP_COMMIT() asm volatile("cp.async.commit_group;" ::: "memory")
#define CP_WAIT0()  asm volatile("cp.async.wait_group 0;" ::: "memory")
#define CP_WAIT1()  asm volatile("cp.async.wait_group 1;" ::: "memory")
#define CP_WAIT2()  asm volatile("cp.async.wait_group 2;" ::: "memory")

// ---------------- prep kernels ----------------
__global__ void k_eq_copy(const int* __restrict__ pq) {
    int i = blockIdx.x * blockDim.x + threadIdx.x;
    if (i < N_) g_eq[i] = pq[i];
}
// merged: flip eq at indices[b] + normalize q/t (+bf16 t) + gather ct_prime (+bf16)
__global__ void k_prep(const float* __restrict__ query, const float* __restrict__ ctgt,
                       const float* __restrict__ pool, const int* __restrict__ indices,
                       const int* __restrict__ pq) {
    int b = blockIdx.x, t = threadIdx.x;
    __shared__ float red[256];
    if (t == 0) {                     // flip (idempotent across duplicate indices)
        int n = indices[b];
        g_eq[n] = 1 - pq[n];
    }
    if (t < 128) {                    // gather ct row; slot = flipped value directly
        int n = indices[b];
        int slot = 1 - pq[n];
        const float4* src = (const float4*)(pool + ((size_t)slot * N_ + (size_t)n) * D_);
        float4 v = src[t];
        ((float4*)(g_ct + b * D_))[t] = v;
        __nv_bfloat162 p0 = __floats2bfloat162_rn(v.x, v.y);
        __nv_bfloat162 p1 = __floats2bfloat162_rn(v.z, v.w);
        uint2 u; u.x = *(uint32_t*)&p0; u.y = *(uint32_t*)&p1;
        ((uint2*)(g_cb + b * D_))[t] = u;
    }
    float x0 = query[b * D_ + t], x1 = query[b * D_ + t + 256];
    red[t] = x0 * x0 + x1 * x1;
    __syncthreads();
    for (int s = 128; s > 0; s >>= 1) { if (t < s) red[t] += red[t + s]; __syncthreads(); }
    float nq = sqrtf(red[0]);
    __syncthreads();
    g_qnorm[b * D_ + t] = x0 / nq;
    g_qnorm[b * D_ + t + 256] = x1 / nq;
    float y0 = ctgt[b * D_ + t], y1 = ctgt[b * D_ + t + 256];
    red[t] = y0 * y0 + y1 * y1;
    __syncthreads();
    for (int s = 128; s > 0; s >>= 1) { if (t < s) red[t] += red[t + s]; __syncthreads(); }
    float nt = sqrtf(red[0]);
    __syncthreads();
    float t0 = y0 / nt, t1 = y1 / nt;
    g_tnorm[b * D_ + t] = t0;
    g_tnorm[b * D_ + t + 256] = t1;
    g_tb[b * D_ + t] = __float2bfloat16(t0);
    g_tb[b * D_ + t + 256] = __float2bfloat16(t1);
}

// ---------------- fused GEMM (512 threads, 16 warps), fp32 score output ----------------
// my = 0: A=g_tb, Brow(k)= k<256 ? tnorm[k] : queue[k],        out=g_St
// my = 1: A=g_cb, Brow(k)= pool[eq[ik],ik],                    out=g_Stp
__global__ __launch_bounds__(512, 1)
void k_gemm3(const float* __restrict__ queue, const float* __restrict__ pool,
             const int* __restrict__ indices, const int* __restrict__ index_queue,
             int my) {
    extern __shared__ __align__(16) char smem[];
    __shared__ const float* rowp[BN];

    const int tid  = threadIdx.x;
    const int lane = tid & 31, wid = tid >> 5;
    const int wm = wid >> 2, wn = wid & 3;          // 4 x 4 warp grid, tile 64x32
    const int bn = blockIdx.x * BN;
    const uint32_t smem_u = (uint32_t)__cvta_generic_to_shared(smem);

    const __nv_bfloat16* Ab = (my == 0) ? g_tb : g_cb;
    float* out = (my == 0) ? g_St : g_Stp;

    if (tid < BN) {
        int kg = bn + tid;
        const float* p;
        if (my == 0) {
            p = (kg < B_) ? (g_tnorm + kg * D_) : (queue + (size_t)kg * D_);
        } else {
            int ik = (kg < B_) ? indices[kg] : index_queue[kg];
            p = pool + ((size_t)g_eq[ik] * N_ + (size_t)ik) * D_;
        }
        rowp[tid] = p;
    }
    __syncthreads();

    float acc[4][4][4];
#pragma unroll
    for (int a = 0; a < 4; a++)
#pragma unroll
        for (int b = 0; b < 4; b++)
#pragma unroll
            for (int c = 0; c < 4; c++) acc[a][b][c] = 0.f;

    const int ar0 = tid >> 2, ac0 = tid & 3;
    const int ar1 = (tid + 512) >> 2, ac1 = (tid + 512) & 3;
    const int br0 = tid >> 3, bc0 = tid & 7;
    const int br1 = (tid + 512) >> 3, bc1 = (tid + 512) & 7;
    const float* bp0 = rowp[br0] + bc0 * 4;
    const float* bp1 = rowp[br1] + bc1 * 4;

#define ISSUE_A(s, kk) do { \
        uint32_t base_ = smem_u + (s) * ASTG; \
        CP_ASYNC16(base_ + ar0 * 80 + ac0 * 16, Ab + (size_t)ar0 * D_ + (kk) + ac0 * 8); \
        CP_ASYNC16(base_ + ar1 * 80 + ac1 * 16, Ab + (size_t)ar1 * D_ + (kk) + ac1 * 8); \
        CP_COMMIT(); \
    } while (0)

#define LOAD_B(kk) do { \
        fb[0] = *(const float4*)(bp0 + (kk)); \
        fb[1] = *(const float4*)(bp1 + (kk)); \
    } while (0)

#define STS_B(s) do { \
        char* base_ = smem + BOFF + (s) * BSTG; \
        { __nv_bfloat162 h0_ = __floats2bfloat162_rn(fb[0].x, fb[0].y); \
          __nv_bfloat162 h1_ = __floats2bfloat162_rn(fb[0].z, fb[0].w); \
          uint2 u_; u_.x = *(uint32_t*)&h0_; u_.y = *(uint32_t*)&h1_; \
          *(uint2*)(base_ + br0 * 80 + bc0 * 8) = u_; } \
        { __nv_bfloat162 h0_ = __floats2bfloat162_rn(fb[1].x, fb[1].y); \
          __nv_bfloat162 h1_ = __floats2bfloat162_rn(fb[1].z, fb[1].w); \
          uint2 u_; u_.x = *(uint32_t*)&h0_; u_.y = *(uint32_t*)&h1_; \
          *(uint2*)(base_ + br1 * 80 + bc1 * 8) = u_; } \
    } while (0)

    float4 fb[2];
    LOAD_B(0);
    ISSUE_A(0, 0); ISSUE_A(1, 32); ISSUE_A(2, 64);
    STS_B(0);
    LOAD_B(32);
    CP_WAIT2();
    __syncthreads();

    const int lrow = lane & 15, lhi = lane >> 4;
#pragma unroll 1
    for (int it = 0; it < 16; ++it) {
        const uint32_t As_u = smem_u + (it & 3) * ASTG;
        const uint32_t Bs_u = smem_u + BOFF + (it & 1) * BSTG;
#pragma unroll
        for (int ks = 0; ks < 2; ks++) {
            uint32_t af[4][4], bf[2][4];
#pragma unroll
            for (int mt = 0; mt < 4; mt++)
                ldsm4(af[mt], As_u + (wm * 64 + mt * 16 + lrow) * 80 + ks * 32 + lhi * 16);
#pragma unroll
            for (int np = 0; np < 2; np++)
                ldsm4(bf[np], Bs_u + (wn * 32 + np * 16 + lrow) * 80 + ks * 32 + lhi * 16);
#pragma unroll
            for (int mt = 0; mt < 4; mt++)
#pragma unroll
                for (int np = 0; np < 2; np++) {
                    mma16816(acc[mt][2 * np],
                             af[mt][0], af[mt][1], af[mt][2], af[mt][3],
                             bf[np][0], bf[np][2]);
                    mma16816(acc[mt][2 * np + 1],
                             af[mt][0], af[mt][1], af[mt][2], af[mt][3],
                             bf[np][1], bf[np][3]);
                }
        }
        if (it < 15) {
            STS_B((it + 1) & 1);
            if (it < 14) LOAD_B((it + 2) * 32);
            if (it + 3 < 16) ISSUE_A((it + 3) & 3, (it + 3) * 32);
            if (it < 13) CP_WAIT2(); else if (it == 13) CP_WAIT1(); else CP_WAIT0();
            __syncthreads();
        }
    }
#undef ISSUE_A
#undef LOAD_B
#undef STS_B

    // epilogue: dist = 2 - 2*ip, fp32 float2 stores
#pragma unroll
    for (int mt = 0; mt < 4; mt++) {
        int r0 = wm * 64 + mt * 16 + (lane >> 2);
#pragma unroll
        for (int nt = 0; nt < 4; nt++) {
            int c = bn + wn * 32 + nt * 8 + (lane & 3) * 2;
            float2 v0, v1;
            v0.x = 2.f - 2.f * acc[mt][nt][0];
            v0.y = 2.f - 2.f * acc[mt][nt][1];
            v1.x = 2.f - 2.f * acc[mt][nt][2];
            v1.y = 2.f - 2.f * acc[mt][nt][3];
            *(float2*)(out + (size_t)r0 * K_ + c)       = v0;
            *(float2*)(out + (size_t)(r0 + 8) * K_ + c) = v1;
        }
    }
}

// ---------------- approx top-CAND per row (R10 code, measured-best) ----------------
__global__ __launch_bounds__(512)
void k_topk2(const float* __restrict__ S, int* __restrict__ outIdx) {
    int b = blockIdx.x;
    const float4* row = (const float4*)(S + (size_t)b * K_);
    float v[TH_]; int id[TH_];
#pragma unroll
    for (int i = 0; i < TH_; i++) { v[i] = FLTMAX; id[i] = 0x7fffffff; }
    float thr = FLTMAX;
    float4 x = row[threadIdx.x];
    for (int k4 = threadIdx.x; k4 < K_ / 4; k4 += 512) {
        int k4n = k4 + 512;
        float4 nx;
        if (k4n < K_ / 4) nx = row[k4n];
        float xs[4] = {x.x, x.y, x.z, x.w};
#pragma unroll
        for (int j = 0; j < 4; j++) {
            float xv = xs[j];
            if (xv < thr) {   // per-thread index increasing -> strict < keeps earliest
                int k = k4 * 4 + j;
                int pos = TH_ - 1;
                while (pos > 0 && xv < v[pos - 1]) {
                    v[pos] = v[pos - 1]; id[pos] = id[pos - 1]; pos--;
                }
                v[pos] = xv; id[pos] = k;
                thr = v[TH_ - 1];
            }
        }
        x = nx;
    }
    __shared__ float swv[16]; __shared__ int swi[16];
    __shared__ int bwi_s;
    int hp = 0;
    for (int r = 0; r < CAND_; r++) {
        float mv = (hp < TH_) ? v[hp] : FLTMAX;
        int   mi = (hp < TH_) ? id[hp] : 0x7fffffff;
        for (int o = 16; o > 0; o >>= 1) {
            float ov = __shfl_down_sync(0xffffffffu, mv, o);
            int   oi = __shfl_down_sync(0xffffffffu, mi, o);
            if (ov < mv || (ov == mv && oi < mi)) { mv = ov; mi = oi; }
        }
        if ((threadIdx.x & 31) == 0) { swv[threadIdx.x >> 5] = mv; swi[threadIdx.x >> 5] = mi; }
        __syncthreads();
        if (threadIdx.x == 0) {
            float bv = swv[0]; int bi = swi[0];
            for (int w = 1; w < 16; w++)
                if (swv[w] < bv || (swv[w] == bv && swi[w] < bi)) { bv = swv[w]; bi = swi[w]; }
            bwi_s = bi;
            outIdx[b * CAND_ + r] = bi;
        }
        __syncthreads();
        if (hp < TH_ && id[hp] == bwi_s) hp++;
        __syncthreads();
    }
}

// ---------------- exact refine (merged): blockIdx.y = mode ----------------
__global__ void k_refine(const float* __restrict__ queue, const float* __restrict__ pool,
                         const int* __restrict__ indices, const int* __restrict__ index_queue) {
    int b = blockIdx.x, mode = blockIdx.y;
    int T = (mode == 0) ? TOPK_ : TOPKP_;
    const int* cand = (mode == 0) ? g_cand1 : g_cand2;
    int* outIdx = (mode == 0) ? g_unidx : g_idxp;
    int lane = threadIdx.x & 31, w = threadIdx.x >> 5;   // 8 warps
    __shared__ float sv[CAND_];
    const float* ar = (mode == 0) ? (g_tnorm + b * D_) : (g_ct + b * D_);
    for (int j = w; j < CAND_; j += 8) {
        int k = cand[b * CAND_ + j];
        const float* rk;
        if (mode == 0) rk = (k < B_) ? (g_tnorm + k * D_) : (queue + (size_t)k * D_);
        else {
            int ik = (k < B_) ? indices[k] : index_queue[k];
            rk = pool + ((size_t)g_eq[ik] * N_ + (size_t)ik) * D_;
        }
        float s = 0.f;
#pragma unroll
        for (int tt = 0; tt < 16; tt++) { int i = tt * 32 + lane; s += ar[i] * rk[i]; }
        for (int o = 16; o > 0; o >>= 1) s += __shfl_down_sync(0xffffffffu, s, o);
        if (lane == 0) sv[j] = 2.f - 2.f * s;
    }
    __syncthreads();
    if (threadIdx.x == 0) {
        float vl[CAND_]; int il[CAND_];
        for (int j = 0; j < CAND_; j++) { vl[j] = sv[j]; il[j] = cand[b * CAND_ + j]; }
        for (int r = 0; r < T; r++) {
            int best = r;
            for (int j = r + 1; j < CAND_; j++)
                if (vl[j] < vl[best] || (vl[j] == vl[best] && il[j] < il[best])) best = j;
            float tv = vl[r]; vl[r] = vl[best]; vl[best] = tv;
            int ti = il[r]; il[r] = il[best]; il[best] = ti;
            outIdx[b * T + r] = il[r];
        }
    }
}

// ---------------- final: exact con-select + loss dots + purity ----------------
__global__ void k_final(const float* __restrict__ queue,
                        const int* __restrict__ labels_bank,
                        const int* __restrict__ labels) {
    int b = blockIdx.x, t = threadIdx.x;
    __shared__ float red[256];
    __shared__ float pv[TOPKP_];
    __shared__ int conIdx[TOPK_];
    const float* qr = g_qnorm + b * D_;
    const float* tr = g_tnorm + b * D_;
    for (int j = 0; j < TOPKP_; j++) {
        int k = g_idxp[b * TOPKP_ + j];
        const float* rk = (k < B_) ? (g_tnorm + k * D_) : (queue + (size_t)k * D_);
        red[t] = tr[t] * rk[t] + tr[t + 256] * rk[t + 256];
        __syncthreads();
        for (int s = 128; s > 0; s >>= 1) { if (t < s) red[t] += red[t + s]; __syncthreads(); }
        if (t == 0) pv[j] = 2.f - 2.f * red[0];
        __syncthreads();
    }
    if (t == 0) {
        float vl[TOPKP_]; int il[TOPKP_];
        for (int j = 0; j < TOPKP_; j++) { vl[j] = pv[j]; il[j] = g_idxp[b * TOPKP_ + j]; }
        for (int r = 0; r < TOPK_; r++) {
            int best = r;
            for (int j = r + 1; j < TOPKP_; j++)
                if (vl[j] < vl[best] || (vl[j] == vl[best] && il[j] < il[best])) best = j;
            float tv = vl[r]; vl[r] = vl[best]; vl[best] = tv;
            int ti = il[r]; il[r] = il[best]; il[best] = ti;
            conIdx[r] = il[r];
        }
    }
    __syncthreads();
    __shared__ float s_un, s_con;
    __shared__ int s_match;
    if (t == 0) { s_un = 0.f; s_con = 0.f; s_match = 0; }
    __syncthreads();
    for (int j = 0; j < 2 * TOPK_; j++) {
        int k = (j < TOPK_) ? g_unidx[b * TOPK_ + j] : conIdx[j - TOPK_];
        const float* rk = (k < B_) ? (g_tnorm + k * D_) : (queue + (size_t)k * D_);
        red[t] = qr[t] * rk[t] + qr[t + 256] * rk[t + 256];
        __syncthreads();
        for (int s = 128; s > 0; s >>= 1) { if (t < s) red[t] += red[t + s]; __syncthreads(); }
        if (t == 0) {
            float d = 2.f - 2.f * red[0];
            if (j < TOPK_) {
                s_un += d;
                int lab = (k < B_) ? labels[k] : labels_bank[k];
                if (lab == labels[b]) s_match++;
            } else {
                s_con += d;
            }
        }
        __syncthreads();
    }
    if (t == 0) {
        g_pb_un[b]  = s_un / (float)TOPK_;
        g_pb_con[b] = s_con / (float)TOPK_;
        g_pb_pur[b] = (float)s_match / (float)TOPK_;
    }
}

__global__ void k_finalize(float* __restrict__ out, int out_size) {
    int t = threadIdx.x;   // 256 threads
    __shared__ float ru[256], rc[256], rp[256];
    ru[t] = g_pb_un[t]; rc[t] = g_pb_con[t]; rp[t] = g_pb_pur[t];
    __syncthreads();
    for (int s = 128; s > 0; s >>= 1) {
        if (t < s) { ru[t] += ru[t + s]; rc[t] += rc[t + s]; rp[t] += rp[t + s]; }
        __syncthreads();
    }
    if (t == 0) {
        float loss = (rc[0] / (float)B_ + ru[0] / (float)B_) * 0.5f;
        out[0] = loss;
        if (out_size > 1) out[1] = rp[0] / (float)B_;
    }
}

// ---------------- launch (fork/join: T0 overlaps G1) ----------------
extern "C" void kernel_launch(void* const* d_in, const int* in_sizes, int n_in,
                              void* d_out, int out_size) {
    const float* query       = (const float*)d_in[0];
    const float* ctgt        = (const float*)d_in[1];
    const float* queue       = (const float*)d_in[2];
    const float* pool        = (const float*)d_in[3];
    const int*   labels_bank = (const int*)d_in[4];
    const int*   index_queue = (const int*)d_in[5];
    const int*   pool_qindex = (const int*)d_in[6];
    const int*   labels      = (const int*)d_in[7];
    const int*   indices     = (const int*)d_in[8];

    float* St_ptr;  cudaGetSymbolAddress((void**)&St_ptr,  g_St);
    float* Stp_ptr; cudaGetSymbolAddress((void**)&Stp_ptr, g_Stp);
    int* c1_ptr; cudaGetSymbolAddress((void**)&c1_ptr, g_cand1);
    int* c2_ptr; cudaGetSymbolAddress((void**)&c2_ptr, g_cand2);

    cudaFuncSetAttribute(k_gemm3, cudaFuncAttributeMaxDynamicSharedMemorySize, GSMEM);

    // lazily created side stream + events (first call is the eager correctness
    // run, not captured; the capture call replays the fork/join pattern)
    static cudaStream_t s2 = nullptr;
    static cudaEvent_t evG0 = nullptr, evT0 = nullptr;
    if (!s2) {
        cudaStreamCreateWithFlags(&s2, cudaStreamNonBlocking);
        cudaEventCreateWithFlags(&evG0, cudaEventDisableTiming);
        cudaEventCreateWithFlags(&evT0, cudaEventDisableTiming);
    }

    k_eq_copy<<<(N_ + 255) / 256, 256>>>(pool_qindex);
    k_prep<<<B_, 256>>>(query, ctgt, pool, indices, pool_qindex);

    // G0 (matrix 0) on main stream, then fork T0 onto s2 while G1 runs
    k_gemm3<<<K_ / BN, 512, GSMEM>>>(queue, pool, indices, index_queue, 0);
    cudaEventRecord(evG0, 0);

    k_gemm3<<<K_ / BN, 512, GSMEM>>>(queue, pool, indices, index_queue, 1);

    cudaStreamWaitEvent(s2, evG0, 0);
    k_topk2<<<B_, 512, 0, s2>>>(St_ptr, c1_ptr);
    cudaEventRecord(evT0, s2);

    k_topk2<<<B_, 512>>>(Stp_ptr, c2_ptr);

    // join: refine needs both candidate sets
    cudaStreamWaitEvent(0, evT0, 0);
    dim3 gr(B_, 2);
    k_refine<<<gr, 256>>>(queue, pool, indices, index_queue);
    k_final<<<B_, 256>>>(queue, labels_bank, labels);
    k_finalize<<<1, 256>>>((float*)d_out, out_size);
}

// round 15
// speedup vs baseline: 3.0115x; 1.4272x over previous
#include <cuda_runtime.h>
#include <cuda_bf16.h>
#include <cstdint>
#include <cstddef>

#define B_    256
#define D_    512
#define K_    128000
#define N_    100000
#define TOPK_  5
#define TOPKP_ 10
#define CAND_  32
#define NBLK_  1000     // score blocks per row (K_ / BN)
#define LCAP   2048     // candidate list capacity
#define FLTMAX 3.402823466e+38f

// GEMM tiling: BM=256, BN=128, BK=32, 16 warps (4M x 4N), warp tile 64x32
#define BN 128
#define ASTG  20480                 // A stage bytes: 256 rows * 80
#define BSTG  10240                 // B (bf16) stage bytes: 128 rows * 80
#define BOFF  (4 * ASTG)            // 81920
#define GSMEM (4 * ASTG + 2 * BSTG) // 102400

// ---------------- device scratch ----------------
__device__ __align__(16) float g_St [32768000];   // fp32 scores, mode 0
__device__ __align__(16) float g_Stp[32768000];   // fp32 scores, mode 1
__device__ __align__(16) float g_bmin[2 * B_ * NBLK_];   // per-row per-block min score
__device__ __align__(16) float g_tnorm[B_ * D_];
__device__ __align__(16) float g_qnorm[B_ * D_];
__device__ __align__(16) float g_ct   [B_ * D_];
__device__ __align__(16) __nv_bfloat16 g_tb[B_ * D_];
__device__ __align__(16) __nv_bfloat16 g_cb[B_ * D_];
__device__ int   g_eq[N_];
__device__ int   g_cand1[B_ * CAND_], g_cand2[B_ * CAND_];
__device__ int   g_unidx[B_ * TOPK_], g_idxp[B_ * TOPKP_];
__device__ float g_pb_un[B_], g_pb_con[B_], g_pb_pur[B_];

// ---------------- MMA / cp.async helpers ----------------
__device__ __forceinline__ void ldsm4(uint32_t* r, uint32_t addr) {
    asm volatile("ldmatrix.sync.aligned.m8n8.x4.shared.b16 {%0,%1,%2,%3}, [%4];"
        : "=r"(r[0]), "=r"(r[1]), "=r"(r[2]), "=r"(r[3]) : "r"(addr));
}
__device__ __forceinline__ void mma16816(float* c,
        uint32_t a0, uint32_t a1, uint32_t a2, uint32_t a3,
        uint32_t b0, uint32_t b1) {
    asm volatile(
        "mma.sync.aligned.m16n8k16.row.col.f32.bf16.bf16.f32 "
        "{%0,%1,%2,%3}, {%4,%5,%6,%7}, {%8,%9}, {%0,%1,%2,%3};"
        : "+f"(c[0]), "+f"(c[1]), "+f"(c[2]), "+f"(c[3])
        : "r"(a0), "r"(a1), "r"(a2), "r"(a3), "r"(b0), "r"(b1));
}
#define CP_ASYNC16(dst_u32, src_ptr) \
    asm volatile("cp.async.cg.shared.global [%0], [%1], 16;" \
        :: "r"(dst_u32), "l"(src_ptr))
#define CP_COMMIT() asm volatile("cp.async.commit_group;" ::: "memory")
#define CP_WAIT0()  asm volatile("cp.async.wait_group 0;" ::: "memory")
#define CP_WAIT1()  asm volatile("cp.async.wait_group 1;" ::: "memory")
#define CP_WAIT2()  asm volatile("cp.async.wait_group 2;" ::: "memory")

// ---------------- prep kernels ----------------
__global__ void k_eq_copy(const int* __restrict__ pq) {
    int i = blockIdx.x * blockDim.x + threadIdx.x;
    if (i < N_) g_eq[i] = pq[i];
}
// merged: flip eq at indices[b] + normalize q/t (+bf16 t) + gather ct_prime (+bf16)
__global__ void k_prep(const float* __restrict__ query, const float* __restrict__ ctgt,
                       const float* __restrict__ pool, const int* __restrict__ indices,
                       const int* __restrict__ pq) {
    int b = blockIdx.x, t = threadIdx.x;
    __shared__ float red[256];
    if (t == 0) {                     // flip (idempotent across duplicate indices)
        int n = indices[b];
        g_eq[n] = 1 - pq[n];
    }
    if (t < 128) {                    // gather ct row; slot = flipped value directly
        int n = indices[b];
        int slot = 1 - pq[n];
        const float4* src = (const float4*)(pool + ((size_t)slot * N_ + (size_t)n) * D_);
        float4 v = src[t];
        ((float4*)(g_ct + b * D_))[t] = v;
        __nv_bfloat162 p0 = __floats2bfloat162_rn(v.x, v.y);
        __nv_bfloat162 p1 = __floats2bfloat162_rn(v.z, v.w);
        uint2 u; u.x = *(uint32_t*)&p0; u.y = *(uint32_t*)&p1;
        ((uint2*)(g_cb + b * D_))[t] = u;
    }
    float x0 = query[b * D_ + t], x1 = query[b * D_ + t + 256];
    red[t] = x0 * x0 + x1 * x1;
    __syncthreads();
    for (int s = 128; s > 0; s >>= 1) { if (t < s) red[t] += red[t + s]; __syncthreads(); }
    float nq = sqrtf(red[0]);
    __syncthreads();
    g_qnorm[b * D_ + t] = x0 / nq;
    g_qnorm[b * D_ + t + 256] = x1 / nq;
    float y0 = ctgt[b * D_ + t], y1 = ctgt[b * D_ + t + 256];
    red[t] = y0 * y0 + y1 * y1;
    __syncthreads();
    for (int s = 128; s > 0; s >>= 1) { if (t < s) red[t] += red[t + s]; __syncthreads(); }
    float nt = sqrtf(red[0]);
    __syncthreads();
    float t0 = y0 / nt, t1 = y1 / nt;
    g_tnorm[b * D_ + t] = t0;
    g_tnorm[b * D_ + t + 256] = t1;
    g_tb[b * D_ + t] = __float2bfloat16(t0);
    g_tb[b * D_ + t + 256] = __float2bfloat16(t1);
}

// ---------------- fused GEMM (512 threads, 16 warps) + per-block row-min epilogue ----
// blockIdx.y = 0: A=g_tb, Brow(k)= k<256 ? tnorm[k] : queue[k],        out=g_St
// blockIdx.y = 1: A=g_cb, Brow(k)= pool[eq[ik],ik],                    out=g_Stp
__global__ __launch_bounds__(512, 1)
void k_gemm3(const float* __restrict__ queue, const float* __restrict__ pool,
             const int* __restrict__ indices, const int* __restrict__ index_queue) {
    extern __shared__ __align__(16) char smem[];
    __shared__ const float* rowp[BN];

    const int my   = blockIdx.y;
    const int tid  = threadIdx.x;
    const int lane = tid & 31, wid = tid >> 5;
    const int wm = wid >> 2, wn = wid & 3;          // 4 x 4 warp grid, tile 64x32
    const int bn = blockIdx.x * BN;
    const uint32_t smem_u = (uint32_t)__cvta_generic_to_shared(smem);

    const __nv_bfloat16* Ab = (my == 0) ? g_tb : g_cb;
    float* out = (my == 0) ? g_St : g_Stp;

    if (tid < BN) {
        int kg = bn + tid;
        const float* p;
        if (my == 0) {
            p = (kg < B_) ? (g_tnorm + kg * D_) : (queue + (size_t)kg * D_);
        } else {
            int ik = (kg < B_) ? indices[kg] : index_queue[kg];
            p = pool + ((size_t)g_eq[ik] * N_ + (size_t)ik) * D_;
        }
        rowp[tid] = p;
    }
    __syncthreads();

    float acc[4][4][4];
#pragma unroll
    for (int a = 0; a < 4; a++)
#pragma unroll
        for (int b = 0; b < 4; b++)
#pragma unroll
            for (int c = 0; c < 4; c++) acc[a][b][c] = 0.f;

    const int ar0 = tid >> 2, ac0 = tid & 3;
    const int ar1 = (tid + 512) >> 2, ac1 = (tid + 512) & 3;
    const int br0 = tid >> 3, bc0 = tid & 7;
    const int br1 = (tid + 512) >> 3, bc1 = (tid + 512) & 7;
    const float* bp0 = rowp[br0] + bc0 * 4;
    const float* bp1 = rowp[br1] + bc1 * 4;

#define ISSUE_A(s, kk) do { \
        uint32_t base_ = smem_u + (s) * ASTG; \
        CP_ASYNC16(base_ + ar0 * 80 + ac0 * 16, Ab + (size_t)ar0 * D_ + (kk) + ac0 * 8); \
        CP_ASYNC16(base_ + ar1 * 80 + ac1 * 16, Ab + (size_t)ar1 * D_ + (kk) + ac1 * 8); \
        CP_COMMIT(); \
    } while (0)

#define LOAD_B(kk) do { \
        fb[0] = *(const float4*)(bp0 + (kk)); \
        fb[1] = *(const float4*)(bp1 + (kk)); \
    } while (0)

#define STS_B(s) do { \
        char* base_ = smem + BOFF + (s) * BSTG; \
        { __nv_bfloat162 h0_ = __floats2bfloat162_rn(fb[0].x, fb[0].y); \
          __nv_bfloat162 h1_ = __floats2bfloat162_rn(fb[0].z, fb[0].w); \
          uint2 u_; u_.x = *(uint32_t*)&h0_; u_.y = *(uint32_t*)&h1_; \
          *(uint2*)(base_ + br0 * 80 + bc0 * 8) = u_; } \
        { __nv_bfloat162 h0_ = __floats2bfloat162_rn(fb[1].x, fb[1].y); \
          __nv_bfloat162 h1_ = __floats2bfloat162_rn(fb[1].z, fb[1].w); \
          uint2 u_; u_.x = *(uint32_t*)&h0_; u_.y = *(uint32_t*)&h1_; \
          *(uint2*)(base_ + br1 * 80 + bc1 * 8) = u_; } \
    } while (0)

    float4 fb[2];
    LOAD_B(0);
    ISSUE_A(0, 0); ISSUE_A(1, 32); ISSUE_A(2, 64);
    STS_B(0);
    LOAD_B(32);
    CP_WAIT2();
    __syncthreads();

    const int lrow = lane & 15, lhi = lane >> 4;
#pragma unroll 1
    for (int it = 0; it < 16; ++it) {
        const uint32_t As_u = smem_u + (it & 3) * ASTG;
        const uint32_t Bs_u = smem_u + BOFF + (it & 1) * BSTG;
#pragma unroll
        for (int ks = 0; ks < 2; ks++) {
            uint32_t af[4][4], bf[2][4];
#pragma unroll
            for (int mt = 0; mt < 4; mt++)
                ldsm4(af[mt], As_u + (wm * 64 + mt * 16 + lrow) * 80 + ks * 32 + lhi * 16);
#pragma unroll
            for (int np = 0; np < 2; np++)
                ldsm4(bf[np], Bs_u + (wn * 32 + np * 16 + lrow) * 80 + ks * 32 + lhi * 16);
#pragma unroll
            for (int mt = 0; mt < 4; mt++)
#pragma unroll
                for (int np = 0; np < 2; np++) {
                    mma16816(acc[mt][2 * np],
                             af[mt][0], af[mt][1], af[mt][2], af[mt][3],
                             bf[np][0], bf[np][2]);
                    mma16816(acc[mt][2 * np + 1],
                             af[mt][0], af[mt][1], af[mt][2], af[mt][3],
                             bf[np][1], bf[np][3]);
                }
        }
        if (it < 15) {
            STS_B((it + 1) & 1);
            if (it < 14) LOAD_B((it + 2) * 32);
            if (it + 3 < 16) ISSUE_A((it + 3) & 3, (it + 3) * 32);
            if (it < 13) CP_WAIT2(); else if (it == 13) CP_WAIT1(); else CP_WAIT0();
            __syncthreads();
        }
    }
#undef ISSUE_A
#undef LOAD_B
#undef STS_B

    // epilogue 1: dist = 2 - 2*ip, fp32 float2 stores
#pragma unroll
    for (int mt = 0; mt < 4; mt++) {
        int r0 = wm * 64 + mt * 16 + (lane >> 2);
#pragma unroll
        for (int nt = 0; nt < 4; nt++) {
            int c = bn + wn * 32 + nt * 8 + (lane & 3) * 2;
            float2 v0, v1;
            v0.x = 2.f - 2.f * acc[mt][nt][0];
            v0.y = 2.f - 2.f * acc[mt][nt][1];
            v1.x = 2.f - 2.f * acc[mt][nt][2];
            v1.y = 2.f - 2.f * acc[mt][nt][3];
            *(float2*)(out + (size_t)r0 * K_ + c)       = v0;
            *(float2*)(out + (size_t)(r0 + 8) * K_ + c) = v1;
        }
    }

    // epilogue 2: per-row block-min (= 2 - 2*max(acc); exact under RN monotonicity)
    __syncthreads();                       // smem stages dead; reuse for row maxes
    float* smax = (float*)smem;            // [4][256]
#pragma unroll
    for (int mt = 0; mt < 4; mt++) {
        float ma = acc[mt][0][0], mb = acc[mt][0][2];
#pragma unroll
        for (int nt = 0; nt < 4; nt++) {
            ma = fmaxf(ma, fmaxf(acc[mt][nt][0], acc[mt][nt][1]));
            mb = fmaxf(mb, fmaxf(acc[mt][nt][2], acc[mt][nt][3]));
        }
#pragma unroll
        for (int o = 1; o <= 2; o <<= 1) {
            ma = fmaxf(ma, __shfl_xor_sync(0xffffffffu, ma, o));
            mb = fmaxf(mb, __shfl_xor_sync(0xffffffffu, mb, o));
        }
        if ((lane & 3) == 0) {
            int r0 = wm * 64 + mt * 16 + (lane >> 2);
            smax[wn * 256 + r0]     = ma;
            smax[wn * 256 + r0 + 8] = mb;
        }
    }
    __syncthreads();
    if (tid < 256) {
        float m = fmaxf(fmaxf(smax[tid], smax[256 + tid]),
                        fmaxf(smax[512 + tid], smax[768 + tid]));
        g_bmin[((size_t)my * B_ + tid) * NBLK_ + blockIdx.x] = 2.f - 2.f * m;
    }
}

// ---------------- topk via block-min pruning (exact top-CAND, tie -> smaller idx) ----
__global__ __launch_bounds__(256)
void k_topk2(int* __restrict__ o1, int* __restrict__ o2) {
    int b = blockIdx.x, my = blockIdx.y;
    const float* S  = (my == 0) ? g_St : g_Stp;
    const float* bm = g_bmin + ((size_t)my * B_ + b) * NBLK_;
    int* outIdx = (my == 0) ? o1 : o2;
    const int t = threadIdx.x;

    __shared__ float smv[1024];
    __shared__ float lv[LCAP];
    __shared__ int   li[LCAP];
    __shared__ int   cnt;
    __shared__ float tau_s;
    __shared__ float swv[8]; __shared__ int swi[8];

    for (int i = t; i < 1024; i += 256) smv[i] = (i < NBLK_) ? bm[i] : FLTMAX;
    if (t == 0) cnt = 0;
    __syncthreads();

    // tau = value of 32nd smallest block-min (extraction; ties by block idx)
    for (int r = 0; r < CAND_; r++) {
        float mv = FLTMAX; int mi = 0x7fffffff;
        for (int i = t; i < 1024; i += 256) {
            float x = smv[i];
            if (x < mv || (x == mv && i < mi)) { mv = x; mi = i; }
        }
        for (int o = 16; o > 0; o >>= 1) {
            float ov = __shfl_down_sync(0xffffffffu, mv, o);
            int   oi = __shfl_down_sync(0xffffffffu, mi, o);
            if (ov < mv || (ov == mv && oi < mi)) { mv = ov; mi = oi; }
        }
        if ((t & 31) == 0) { swv[t >> 5] = mv; swi[t >> 5] = mi; }
        __syncthreads();
        if (t == 0) {
            float bv = swv[0]; int bi = swi[0];
            for (int w2 = 1; w2 < 8; w2++)
                if (swv[w2] < bv || (swv[w2] == bv && swi[w2] < bi)) { bv = swv[w2]; bi = swi[w2]; }
            smv[bi] = FLTMAX;
            if (r == CAND_ - 1) tau_s = bv;
        }
        __syncthreads();
    }
    float tau = tau_s;

    // collect all elements <= tau from blocks with min <= tau
    int w = t >> 5, lane = t & 31;
    for (int j = w; j < NBLK_; j += 8) {
        if (bm[j] <= tau) {
            const float4* blk = (const float4*)(S + (size_t)b * K_ + j * BN);
            float4 v = blk[lane];             // 32 lanes x 4 = 128 cols
            int cb = j * BN + lane * 4;
            if (v.x <= tau) { int p = atomicAdd(&cnt, 1); if (p < LCAP) { lv[p] = v.x; li[p] = cb + 0; } }
            if (v.y <= tau) { int p = atomicAdd(&cnt, 1); if (p < LCAP) { lv[p] = v.y; li[p] = cb + 1; } }
            if (v.z <= tau) { int p = atomicAdd(&cnt, 1); if (p < LCAP) { lv[p] = v.z; li[p] = cb + 2; } }
            if (v.w <= tau) { int p = atomicAdd(&cnt, 1); if (p < LCAP) { lv[p] = v.w; li[p] = cb + 3; } }
        }
    }
    __syncthreads();
    int n = (cnt < LCAP) ? cnt : LCAP;

    // warp 0 selects top-CAND by (value, index)
    if (w == 0) {
        for (int r = 0; r < CAND_; r++) {
            float mv = FLTMAX; int mi = 0x7fffffff; int mp = -1;
            for (int i = lane; i < n; i += 32) {
                float x = lv[i]; int ix = li[i];
                if (x < mv || (x == mv && ix < mi)) { mv = x; mi = ix; mp = i; }
            }
            for (int o = 16; o > 0; o >>= 1) {
                float ov = __shfl_down_sync(0xffffffffu, mv, o);
                int   oi = __shfl_down_sync(0xffffffffu, mi, o);
                int   op = __shfl_down_sync(0xffffffffu, mp, o);
                if (ov < mv || (ov == mv && oi < mi)) { mv = ov; mi = oi; mp = op; }
            }
            mi = __shfl_sync(0xffffffffu, mi, 0);
            mp = __shfl_sync(0xffffffffu, mp, 0);
            if (lane == 0) {
                outIdx[b * CAND_ + r] = mi;
                if (mp >= 0) { lv[mp] = FLTMAX; li[mp] = 0x7fffffff; }
            }
            __syncwarp();
        }
    }
}

// ---------------- exact refine (merged): blockIdx.y = mode ----------------
__global__ void k_refine(const float* __restrict__ queue, const float* __restrict__ pool,
                         const int* __restrict__ indices, const int* __restrict__ index_queue) {
    int b = blockIdx.x, mode = blockIdx.y;
    int T = (mode == 0) ? TOPK_ : TOPKP_;
    const int* cand = (mode == 0) ? g_cand1 : g_cand2;
    int* outIdx = (mode == 0) ? g_unidx : g_idxp;
    int lane = threadIdx.x & 31, w = threadIdx.x >> 5;   // 8 warps
    __shared__ float sv[CAND_];
    const float* ar = (mode == 0) ? (g_tnorm + b * D_) : (g_ct + b * D_);
    for (int j = w; j < CAND_; j += 8) {
        int k = cand[b * CAND_ + j];
        const float* rk;
        if (mode == 0) rk = (k < B_) ? (g_tnorm + k * D_) : (queue + (size_t)k * D_);
        else {
            int ik = (k < B_) ? indices[k] : index_queue[k];
            rk = pool + ((size_t)g_eq[ik] * N_ + (size_t)ik) * D_;
        }
        float s = 0.f;
#pragma unroll
        for (int tt = 0; tt < 16; tt++) { int i = tt * 32 + lane; s += ar[i] * rk[i]; }
        for (int o = 16; o > 0; o >>= 1) s += __shfl_down_sync(0xffffffffu, s, o);
        if (lane == 0) sv[j] = 2.f - 2.f * s;
    }
    __syncthreads();
    if (threadIdx.x == 0) {
        float vl[CAND_]; int il[CAND_];
        for (int j = 0; j < CAND_; j++) { vl[j] = sv[j]; il[j] = cand[b * CAND_ + j]; }
        for (int r = 0; r < T; r++) {
            int best = r;
            for (int j = r + 1; j < CAND_; j++)
                if (vl[j] < vl[best] || (vl[j] == vl[best] && il[j] < il[best])) best = j;
            float tv = vl[r]; vl[r] = vl[best]; vl[best] = tv;
            int ti = il[r]; il[r] = il[best]; il[best] = ti;
            outIdx[b * T + r] = il[r];
        }
    }
}

// ---------------- final: exact con-select + loss dots + purity ----------------
__global__ void k_final(const float* __restrict__ queue,
                        const int* __restrict__ labels_bank,
                        const int* __restrict__ labels) {
    int b = blockIdx.x, t = threadIdx.x;
    __shared__ float red[256];
    __shared__ float pv[TOPKP_];
    __shared__ int conIdx[TOPK_];
    const float* qr = g_qnorm + b * D_;
    const float* tr = g_tnorm + b * D_;
    for (int j = 0; j < TOPKP_; j++) {
        int k = g_idxp[b * TOPKP_ + j];
        const float* rk = (k < B_) ? (g_tnorm + k * D_) : (queue + (size_t)k * D_);
        red[t] = tr[t] * rk[t] + tr[t + 256] * rk[t + 256];
        __syncthreads();
        for (int s = 128; s > 0; s >>= 1) { if (t < s) red[t] += red[t + s]; __syncthreads(); }
        if (t == 0) pv[j] = 2.f - 2.f * red[0];
        __syncthreads();
    }
    if (t == 0) {
        float vl[TOPKP_]; int il[TOPKP_];
        for (int j = 0; j < TOPKP_; j++) { vl[j] = pv[j]; il[j] = g_idxp[b * TOPKP_ + j]; }
        for (int r = 0; r < TOPK_; r++) {
            int best = r;
            for (int j = r + 1; j < TOPKP_; j++)
                if (vl[j] < vl[best] || (vl[j] == vl[best] && il[j] < il[best])) best = j;
            float tv = vl[r]; vl[r] = vl[best]; vl[best] = tv;
            int ti = il[r]; il[r] = il[best]; il[best] = ti;
            conIdx[r] = il[r];
        }
    }
    __syncthreads();
    __shared__ float s_un, s_con;
    __shared__ int s_match;
    if (t == 0) { s_un = 0.f; s_con = 0.f; s_match = 0; }
    __syncthreads();
    for (int j = 0; j < 2 * TOPK_; j++) {
        int k = (j < TOPK_) ? g_unidx[b * TOPK_ + j] : conIdx[j - TOPK_];
        const float* rk = (k < B_) ? (g_tnorm + k * D_) : (queue + (size_t)k * D_);
        red[t] = qr[t] * rk[t] + qr[t + 256] * rk[t + 256];
        __syncthreads();
        for (int s = 128; s > 0; s >>= 1) { if (t < s) red[t] += red[t + s]; __syncthreads(); }
        if (t == 0) {
            float d = 2.f - 2.f * red[0];
            if (j < TOPK_) {
                s_un += d;
                int lab = (k < B_) ? labels[k] : labels_bank[k];
                if (lab == labels[b]) s_match++;
            } else {
                s_con += d;
            }
        }
        __syncthreads();
    }
    if (t == 0) {
        g_pb_un[b]  = s_un / (float)TOPK_;
        g_pb_con[b] = s_con / (float)TOPK_;
        g_pb_pur[b] = (float)s_match / (float)TOPK_;
    }
}

__global__ void k_finalize(float* __restrict__ out, int out_size) {
    int t = threadIdx.x;   // 256 threads
    __shared__ float ru[256], rc[256], rp[256];
    ru[t] = g_pb_un[t]; rc[t] = g_pb_con[t]; rp[t] = g_pb_pur[t];
    __syncthreads();
    for (int s = 128; s > 0; s >>= 1) {
        if (t < s) { ru[t] += ru[t + s]; rc[t] += rc[t + s]; rp[t] += rp[t + s]; }
        __syncthreads();
    }
    if (t == 0) {
        float loss = (rc[0] / (float)B_ + ru[0] / (float)B_) * 0.5f;
        out[0] = loss;
        if (out_size > 1) out[1] = rp[0] / (float)B_;
    }
}

// ---------------- launch ----------------
extern "C" void kernel_launch(void* const* d_in, const int* in_sizes, int n_in,
                              void* d_out, int out_size) {
    const float* query       = (const float*)d_in[0];
    const float* ctgt        = (const float*)d_in[1];
    const float* queue       = (const float*)d_in[2];
    const float* pool        = (const float*)d_in[3];
    const int*   labels_bank = (const int*)d_in[4];
    const int*   index_queue = (const int*)d_in[5];
    const int*   pool_qindex = (const int*)d_in[6];
    const int*   labels      = (const int*)d_in[7];
    const int*   indices     = (const int*)d_in[8];

    int* c1_ptr; cudaGetSymbolAddress((void**)&c1_ptr, g_cand1);
    int* c2_ptr; cudaGetSymbolAddress((void**)&c2_ptr, g_cand2);

    cudaFuncSetAttribute(k_gemm3, cudaFuncAttributeMaxDynamicSharedMemorySize, GSMEM);

    // launch #1
    k_eq_copy<<<(N_ + 255) / 256, 256>>>(pool_qindex);
    // launch #2
    k_prep<<<B_, 256>>>(query, ctgt, pool, indices, pool_qindex);
    // launch #3
    dim3 gg(K_ / BN, 2);
    k_gemm3<<<gg, 512, GSMEM>>>(queue, pool, indices, index_queue);
    // launch #4  <-- ncu capture slot
    dim3 gt(B_, 2);
    k_topk2<<<gt, 256>>>(c1_ptr, c2_ptr);
    // launch #5
    dim3 gr(B_, 2);
    k_refine<<<gr, 256>>>(queue, pool, indices, index_queue);
    // launch #6
    k_final<<<B_, 256>>>(queue, labels_bank, labels);
    // launch #7
    k_finalize<<<1, 256>>>((float*)d_out, out_size);
}